// round 11
// baseline (speedup 1.0000x reference)
#include <cuda_runtime.h>
#include <cstdint>

#define SEQ   2048
#define HID   512
#define TAPS  64
#define SC    64        // seq rows per CTA
#define UGRP  8         // rows per group
#define NG    (SC / UGRP)
#define HTAPS 32        // taps per thread-half
#define NPAIR 256       // u64 channel-pairs per row
#define RING  80        // ring rows in smem

typedef unsigned long long u64;

__device__ __forceinline__ u64 fma2(u64 a, u64 b, u64 c) {
    u64 d;
    asm("fma.rn.f32x2 %0, %1, %2, %3;" : "=l"(d) : "l"(a), "l"(b), "l"(c));
    return d;
}
__device__ __forceinline__ u64 add2(u64 a, u64 b) {
    u64 d;
    asm("add.rn.f32x2 %0, %1, %2;" : "=l"(d) : "l"(a), "l"(b));
    return d;
}
__device__ __forceinline__ float lo32(u64 v) { return __uint_as_float((unsigned)v); }
__device__ __forceinline__ float hi32(u64 v) { return __uint_as_float((unsigned)(v >> 32)); }
__device__ __forceinline__ u64 pack2(float l, float h) {
    return ((u64)__float_as_uint(h) << 32) | (u64)__float_as_uint(l);
}

#define CP8(dst_u32, src_ptr) \
    asm volatile("cp.async.ca.shared.global [%0], [%1], 8;" :: "r"(dst_u32), "l"(src_ptr))
#define CPCOMMIT() asm volatile("cp.async.commit_group;" ::: "memory")
#define CPWAIT0()  asm volatile("cp.async.wait_group 0;"  ::: "memory")

// Fused circular depthwise conv (64 taps, f32x2) + residual + LayerNorm.
// 512 threads = 256 channel-pairs x 2 tap-halves, FULLY SYMMETRIC roles:
// both halves run 32 taps off the cp.async smem ring via a static 8-register
// circular band, exchange partials both ways through part[2], both compute
// the LN reduction (stage-2 warp-redundant), and split the stores by rows.
extern __shared__ u64 dsm[];

__global__ __launch_bounds__(512, 1) void fconv_ln_kernel(
    const float* __restrict__ x,
    const float* __restrict__ w,
    const float* __restrict__ gamma,
    const float* __restrict__ beta,
    float* __restrict__ out)
{
    u64*    ring = dsm;                                   // [RING][NPAIR] 160KB
    u64*    part = dsm + RING * NPAIR;                    // [2][UGRP][NPAIR] 32KB
    float2* red  = reinterpret_cast<float2*>(part + 2 * UGRP * NPAIR); // [8][17]

    const int tid  = threadIdx.x;
    const int lane = tid & 31;
    const int widx = tid >> 5;            // 0..15
    const int p    = tid & (NPAIR - 1);   // channel pair
    const int h    = tid >> 8;            // tap half: taps [32h, 32h+32)
    const int b    = blockIdx.y;
    const int s0   = blockIdx.x * SC;

    const u64* __restrict__ xb =
        reinterpret_cast<const u64*>(x) + (size_t)b * SEQ * NPAIR;

    const unsigned rbase = (unsigned)__cvta_generic_to_shared(ring);
    const u64* __restrict__ ringp = ring + p;

    // Prologue: rows s0-63..s0+7 -> slots 1..71; halves interleave rows.
    // slot(row) = (row - s0 + 64) mod RING.
#pragma unroll 1
    for (int i = h; i < 71; i += 2) {
        int rowg = (s0 - 63 + i + SEQ) & (SEQ - 1);
        CP8(rbase + (unsigned)(((i + 1) * NPAIR + p) * 8),
            xb + (size_t)rowg * NPAIR + p);
    }
    CPCOMMIT();

    // This half's 32 tap-weights (registers). Overlaps prologue fill.
    u64 wr[HTAPS];
#pragma unroll
    for (int t = 0; t < HTAPS; ++t)
        wr[t] = reinterpret_cast<const u64*>(w)[(HTAPS * h + t) * NPAIR + p];

    const float ksc = 0.022097086912079608f;   // 1/sqrt(2048)
    const u64 sc2 = pack2(ksc, ksc);

#pragma unroll 1
    for (int g = 0; g < NG; ++g) {
        CPWAIT0();
        __syncthreads();   // sync0: ring rows visible; prev part fully consumed

        // Early prefetch for group g+1: rows sb+8..sb+15 -> slots (8g+72..79)%RING,
        // disjoint from this group's read slots (8g+1..8g+71)%RING. 4 rows/half.
        if (g < NG - 1) {
            int slp = 8 * g + 72; if (slp >= RING) slp -= RING;
#pragma unroll
            for (int i = 0; i < 4; ++i) {
                int r = 4 * h + i;
                int rowg = (s0 + 8 * g + 8 + r) & (SEQ - 1);
                CP8(rbase + (unsigned)(((slp + r) * NPAIR + p) * 8),
                    xb + (size_t)rowg * NPAIR + p);
            }
        }
        CPCOMMIT();

        // Band init: this half's base row r0 = sb - 32h at slot bsl (mult of 8).
        int sli0 = 8 * g + 64; if (sli0 >= RING) sli0 -= RING;       // slot of sb
        int bsl  = sli0 - HTAPS * h; if (bsl < 0) bsl += RING;

        u64 band[8];
#pragma unroll
        for (int i = 0; i < 8; ++i) band[i] = ringp[(bsl + i) * NPAIR];

        u64 acc[8];
#pragma unroll
        for (int j = 0; j < 8; ++j) acc[j] = 0ull;

        // Descending history stream: rows r0-1-t, t = 0..30.
        int sl = bsl ? bsl - 1 : RING - 1;
#pragma unroll
        for (int t = 0; t < HTAPS; ++t) {
            u64 nv = 0ull;
            if (t < HTAPS - 1) {
                nv = ringp[sl * NPAIR];
                sl = sl ? sl - 1 : RING - 1;
            }
#pragma unroll
            for (int j = 0; j < 8; ++j)
                acc[j] = fma2(wr[t], band[(j - t) & 7], acc[j]);
            if (t < HTAPS - 1) band[(7 - t) & 7] = nv;
        }

        // Symmetric partial exchange.
        {
            u64* pp = part + (h * UGRP) * NPAIR + p;
#pragma unroll
            for (int j = 0; j < 8; ++j) pp[j * NPAIR] = acc[j];
        }
        __syncthreads();   // sync1: partials visible
        {
            const u64* po = part + ((1 - h) * UGRP) * NPAIR + p;
#pragma unroll
            for (int j = 0; j < 8; ++j) {
                u64 tot = add2(acc[j], po[j * NPAIR]);
                acc[j] = fma2(tot, sc2, ringp[(sli0 + j) * NPAIR]); // + residual
            }
        }

        // LN stage 1: per-warp (sum, sumsq) per row. Each channel appears in
        // exactly 2 warps (both halves) -> totals are 2x; divide by 1024.
#pragma unroll
        for (int j = 0; j < 8; ++j) {
            float a = lo32(acc[j]), c = hi32(acc[j]);
            float s = a + c, q = a * a + c * c;
#pragma unroll
            for (int o = 16; o > 0; o >>= 1) {
                s += __shfl_xor_sync(0xFFFFFFFFu, s, o);
                q += __shfl_xor_sync(0xFFFFFFFFu, q, o);
            }
            if (lane == 0) red[j * 17 + widx] = make_float2(s, q);
        }
        __syncthreads();   // sync2: red ready

        // Stage 2, warp-redundant: lanes 0..7 reduce row=lane over 16 warps.
        float mean = 0.f, inv = 0.f;
        if (lane < 8) {
            float s = 0.f, q = 0.f;
#pragma unroll
            for (int i = 0; i < 16; ++i) {
                float2 pr = red[lane * 17 + i];
                s += pr.x; q += pr.y;
            }
            mean = s * (1.0f / (2 * HID));
            float var = q * (1.0f / (2 * HID)) - mean * mean;
            inv = rsqrtf(var + 1e-12f);
        }

        // Stores split by half: h=0 -> rows 0..3, h=1 -> rows 4..7.
        const u64 g2 = reinterpret_cast<const u64*>(gamma)[p];
        const u64 b2 = reinterpret_cast<const u64*>(beta)[p];
        u64* __restrict__ op =
            reinterpret_cast<u64*>(out) + ((size_t)b * SEQ + s0 + 8 * g) * NPAIR + p;
#pragma unroll
        for (int jj = 0; jj < 4; ++jj) {
            int j = 4 * h + jj;
            float mj = __shfl_sync(0xFFFFFFFFu, mean, j);
            float ij = __shfl_sync(0xFFFFFFFFu, inv,  j);
            float a = (lo32(acc[j]) - mj) * ij;
            float c = (hi32(acc[j]) - mj) * ij;
            op[j * NPAIR] =
                pack2(lo32(g2) * a + lo32(b2), hi32(g2) * c + hi32(b2));
        }
    }
}

extern "C" void kernel_launch(void* const* d_in, const int* in_sizes, int n_in,
                              void* d_out, int out_size)
{
    const float* x     = (const float*)d_in[0];   // [B, 2048, 512] f32
    const float* w     = (const float*)d_in[1];   // [1, 64, 512]   f32
    const float* gamma = (const float*)d_in[2];   // [512]          f32
    const float* beta  = (const float*)d_in[3];   // [512]          f32
    float* out = (float*)d_out;

    const int B = in_sizes[0] / (SEQ * HID);
    const int smem = (RING * NPAIR + 2 * UGRP * NPAIR) * 8 + 8 * 17 * 8; // ~193KB

    static bool attr_set = false;
    if (!attr_set) {
        cudaFuncSetAttribute(fconv_ln_kernel,
                             cudaFuncAttributeMaxDynamicSharedMemorySize, smem);
        attr_set = true;
    }

    dim3 grid(SEQ / SC, B);   // (32, B)
    fconv_ln_kernel<<<grid, 512, smem>>>(x, w, gamma, beta, out);
}